// round 12
// baseline (speedup 1.0000x reference)
#include <cuda_runtime.h>
#include <cuda_fp16.h>
#include <cstdint>

// Problem constants
#define B_    8
#define C_    256
#define HIN   160
#define HP    161
#define NH    23          // windows per side
#define WSS   49
#define NPIX  (HP*HP)     // 25921 == 529*49 (window-linear == row-major linear)

typedef unsigned long long ull;

// Scratch (static device arrays — no runtime allocation)
__device__ float  g_qkf[(size_t)B_ * 64 * NPIX];        // q (ch 0..31) + k (ch 32..63)
__device__ float  g_Spart[(size_t)B_ * NH * WSS * WSS]; // per-window-row logit partials
__device__ float  g_attn[(size_t)B_ * WSS * WSS];       // softmax result
__device__ __half g_Wvh[C_ * C_];                       // Wv in fp16 (row-major, K contiguous)

// ---- packed f32x2 helpers ----
__device__ __forceinline__ ull pack2(float x, float y) {
    ull r; asm("mov.b64 %0, {%1, %2};" : "=l"(r) : "f"(x), "f"(y)); return r;
}
__device__ __forceinline__ float2 unpack2(ull v) {
    float2 r; asm("mov.b64 {%0, %1}, %2;" : "=f"(r.x), "=f"(r.y) : "l"(v)); return r;
}
__device__ __forceinline__ void fma2(ull &acc, ull a, ull b) {
    asm("fma.rn.f32x2 %0, %1, %2, %0;" : "+l"(acc) : "l"(a), "l"(b));
}
__device__ __forceinline__ uint32_t smem_u32(const void* p) {
    uint32_t a;
    asm("{ .reg .u64 t; cvta.to.shared.u64 t, %1; cvt.u32.u64 %0, t; }" : "=r"(a) : "l"(p));
    return a;
}
// cp.async (LDGSTS)
__device__ __forceinline__ void cp_async16(uint32_t dst, const void* src, int src_size) {
    asm volatile("cp.async.cg.shared.global [%0], [%1], 16, %2;"
                 :: "r"(dst), "l"(src), "r"(src_size) : "memory");
}
#define CP_COMMIT() asm volatile("cp.async.commit_group;" ::: "memory")
#define CP_WAIT(n)  asm volatile("cp.async.wait_group %0;" :: "n"(n) : "memory")

// warp MMA: D(16x8,f32) += A(16x16,f16 row) * B(16x8,f16 col)
__device__ __forceinline__ void mma_f16(float& d0, float& d1, float& d2, float& d3,
                                        uint32_t a0, uint32_t a1, uint32_t a2, uint32_t a3,
                                        uint32_t b0, uint32_t b1) {
    asm volatile("mma.sync.aligned.m16n8k16.row.col.f32.f16.f16.f32 "
                 "{%0,%1,%2,%3}, {%4,%5,%6,%7}, {%8,%9}, {%0,%1,%2,%3};"
                 : "+f"(d0), "+f"(d1), "+f"(d2), "+f"(d3)
                 : "r"(a0), "r"(a1), "r"(a2), "r"(a3), "r"(b0), "r"(b1));
}

// ---- Kernel A (R6 version): fused q/k 1x1 conv, fp32 FFMA2 ----
#define KA_SMEM ((64 * 256 + 8 * 128) * 4)
__global__ __launch_bounds__(256, 3) void kA(
    const float* __restrict__ x,
    const float* __restrict__ Wq, const float* __restrict__ bq,
    const float* __restrict__ Wk, const float* __restrict__ bk)
{
    extern __shared__ float sm[];
    float* ws = sm;              // 64*256 weights
    float* xs = sm + 64 * 256;   // 8 c-slices x 128 px
    const int b = blockIdx.y;
    const int pxbase = blockIdx.x * 128;
    const int tid = threadIdx.x;

    for (int i = tid; i < 64 * 256; i += 256) {
        int ch = i >> 8, cc = i & 255;
        ws[i] = (ch < 32) ? Wq[ch * 256 + cc] : Wk[(ch - 32) * 256 + cc];
    }
    const int cg = tid >> 4, pg = tid & 15;

    ull acc[4][4];
#pragma unroll
    for (int k = 0; k < 4; k++) {
        int ch = cg * 4 + k;
        float bias = (ch < 32) ? bq[ch] : bk[ch - 32];
#pragma unroll
        for (int m = 0; m < 4; m++) acc[k][m] = pack2(bias, bias);
    }

    for (int c0 = 0; c0 < 256; c0 += 8) {
        __syncthreads();
#pragma unroll
        for (int t = 0; t < 4; t++) {
            int i = tid + 256 * t;
            int cc = i >> 7, px = i & 127;
            int pp = pxbase + px;
            float v = 0.f;
            if (pp < NPIX) {
                int py = pp / HP, pxx = pp - py * HP;
                int sy = (py < HIN) ? py : 158;
                int sx = (pxx < HIN) ? pxx : 158;
                v = x[(((size_t)b * C_ + (c0 + cc)) * HIN + sy) * HIN + sx];
            }
            xs[cc * 128 + px] = v;
        }
        __syncthreads();
#pragma unroll
        for (int cc = 0; cc < 8; cc++) {
            ull w2[4];
#pragma unroll
            for (int k = 0; k < 4; k++) {
                float w = ws[(cg * 4 + k) * 256 + c0 + cc];
                w2[k] = pack2(w, w);
            }
#pragma unroll
            for (int m = 0; m < 4; m++) {
                ull x2 = *(const ull*)(xs + cc * 128 + pg * 2 + 32 * m);
#pragma unroll
                for (int k = 0; k < 4; k++) fma2(acc[k][m], w2[k], x2);
            }
        }
    }
#pragma unroll
    for (int k = 0; k < 4; k++) {
        int ch = cg * 4 + k;
        size_t base = ((size_t)b * 64 + ch) * NPIX;
#pragma unroll
        for (int m = 0; m < 4; m++) {
            float2 v = unpack2(acc[k][m]);
            int pp0 = pxbase + pg * 2 + 32 * m;
            if (pp0 < NPIX)     g_qkf[base + pp0]     = v.x;
            if (pp0 + 1 < NPIX) g_qkf[base + pp0 + 1] = v.y;
        }
    }
}

// ---- Kernel B: logit partials via 7x7 register-tiled outer products ----
#define KB_QK_PAD 3200
#define KB_SMEM ((KB_QK_PAD + 4 * 3136) * 4)   // 62,976 B
__global__ __launch_bounds__(256) void kB()
{
    extern __shared__ float sb[];
    float* qk  = sb;                 // 64 x 49 staged window (+ padding)
    float* red = sb + KB_QK_PAD;     // 4 slices x 64 tiles x 49
    const int b = blockIdx.y, wy = blockIdx.x, tid = threadIdx.x;
    const int slice = tid >> 6;
    const int tile  = tid & 63;
    const int tp = (tile >> 3) * 7;
    const int tq = (tile & 7) * 7;

    if (tid < KB_QK_PAD - 3136) qk[3136 + tid] = 0.f;

    float acc[7][7];
#pragma unroll
    for (int j = 0; j < 7; j++)
#pragma unroll
        for (int jq = 0; jq < 7; jq++) acc[j][jq] = 0.f;

    const int ch0 = tid / 49;
    const int j0  = tid - ch0 * 49;

    for (int wx = 0; wx < NH; wx++) {
        __syncthreads();
        {
            int ch = ch0, j = j0;
            int jd = j / 7, jm = j - jd * 7;
#pragma unroll
            for (int t = 0; t < 13; t++) {
                int i = tid + 256 * t;
                if (i < 3136) {
                    int py = wy * 7 + jd, px = wx * 7 + jm;
                    qk[i] = g_qkf[((size_t)b * 64 + ch) * NPIX + py * HP + px];
                }
                ch += 5; j += 11; jd += 1; jm += 4;
                if (jm >= 7) { jm -= 7; jd += 1; }
                if (j >= 49) { j -= 49; jd -= 7; ch += 1; }
            }
        }
        __syncthreads();
#pragma unroll
        for (int c = 0; c < 8; c++) {
            const float* qrow = qk + (slice * 8 + c) * 49 + tp;
            const float* krow = qk + (32 + slice * 8 + c) * 49 + tq;
            float qv[7], kv[7];
#pragma unroll
            for (int j = 0; j < 7; j++) qv[j] = qrow[j];
#pragma unroll
            for (int j = 0; j < 7; j++) kv[j] = krow[j];
#pragma unroll
            for (int j = 0; j < 7; j++)
#pragma unroll
                for (int jq = 0; jq < 7; jq++)
                    acc[j][jq] = fmaf(qv[j], kv[jq], acc[j][jq]);
        }
    }

    {
        float* r = red + slice * 3136 + tile * 49;
#pragma unroll
        for (int j = 0; j < 7; j++)
#pragma unroll
            for (int jq = 0; jq < 7; jq++) r[j * 7 + jq] = acc[j][jq];
    }
    __syncthreads();
    for (int i = tid; i < 2401; i += 256) {
        int p = i / 49, q = i - (i / 49) * 49;
        int pr = p / 7, j = p - pr * 7;
        int qr = q / 7, jq = q - qr * 7;
        int idx = (pr * 8 + qr) * 49 + j * 7 + jq;
        float s = red[idx] + red[3136 + idx] + red[2 * 3136 + idx] + red[3 * 3136 + idx];
        g_Spart[((size_t)b * NH + wy) * 2401 + i] = s;
    }
}

// ---- Kernel C: softmax (blocks 0..7) + Wv fp16 convert (blocks 8..263) ----
__global__ __launch_bounds__(256) void kC(const float* __restrict__ Wv)
{
    if (blockIdx.x >= 8) {
        int idx = (blockIdx.x - 8) * 256 + threadIdx.x;
        g_Wvh[idx] = __float2half(Wv[idx]);
        return;
    }
    __shared__ float S[2401];
    const int b = blockIdx.x, tid = threadIdx.x;
    for (int i = tid; i < 2401; i += 256) {
        float s = 0.f;
        for (int wy = 0; wy < NH; wy++) s += g_Spart[((size_t)b * NH + wy) * 2401 + i];
        S[i] = s;
    }
    __syncthreads();
    if (tid < 49) {
        const int i = tid;
        float m = -1e30f;
#pragma unroll
        for (int j = 0; j < 49; j++) m = fmaxf(m, S[i * 49 + j]);
        float sum = 0.f;
#pragma unroll
        for (int j = 0; j < 49; j++) sum += expf(S[i * 49 + j] - m);
        float inv = 1.f / sum;
#pragma unroll
        for (int j = 0; j < 49; j++)
            g_attn[(size_t)b * 2401 + i * 49 + j] = expf(S[i * 49 + j] - m) * inv;
    }
}

// ---- Kernel D12: fused  Y = X_win @ attn^T  then  out = Wv @ Y + bv  ----
// MMA1: M=256 (c), N=56 (i), K=64 (j).  MMA2: M=256 (ch), N=56 (i), K=256 (c).
// Smem union: [As 256x72 | Bs 56x72] overlapped by [Wv chunk buf0|buf1 256x40 each],
// then Ys 56x264 (fp16, rows padded for conflict-free B-frag loads).
#define LD1  72
#define LDA2 40
#define LDY  264
#define OFF_BS  (256 * LD1)                 // 18432 halfs
#define OFF_WV1 (256 * LDA2)                // 10240 halfs
#define OFF_YS  (256 * LD1 + 56 * LD1)      // 22464 halfs
#define KD12_SMEM ((OFF_YS + 56 * LDY) * 2) // 74,496 B
__global__ __launch_bounds__(256, 2) void kD12(
    const float* __restrict__ x, const float* __restrict__ bv, float* __restrict__ out)
{
    extern __shared__ __half hs[];
    __half* As = hs;                  // [c][j]
    __half* Bs = hs + OFF_BS;         // [i][j]
    __half* Ys = hs + OFF_YS;         // [i][c] padded rows
    __shared__ int ntab[56];
    const uint32_t smb = smem_u32(hs);
    const int b = blockIdx.y, win = blockIdx.x;
    const int wy = win / 23, wx = win - wy * 23;
    const int tid = threadIdx.x;
    const int lane = tid & 31, w = tid >> 5;
    const int gid = lane >> 2, t4 = lane & 3;

    // output column table (crop + torch-view scramble: lin = wy*1127 + wx*49 + i)
    if (tid < 56) {
        int t = -1;
        if (tid < 49) {
            int lin = wy * 1127 + wx * 49 + tid;
            int hh = lin / HP, ww = lin - hh * HP;
            if (hh < HIN && ww < HIN) t = hh * HIN + ww;
        }
        ntab[tid] = t;
    }
    // zero pads: As j in [48,64), Bs fully, Ys rows 49..55
    for (int i = tid; i < 256 * 8; i += 256) {
        int r = i >> 3, q = i & 7;
        *(uint32_t*)(As + r * LD1 + 48 + q * 2) = 0;
    }
    for (int i = tid; i < 56 * LD1 / 2; i += 256) ((uint32_t*)Bs)[i] = 0;
    for (int i = tid; i < 7 * LDY / 2; i += 256) ((uint32_t*)(Ys + 49 * LDY))[i] = 0;
    __syncthreads();

    // stage X (gather, incremental indexing) and attn, both as fp16
    {
        int c = tid / 49, j = tid - (tid / 49) * 49;
        int jd = j / 7, jm = j - jd * 7;
        const float* xb = x + (size_t)b * C_ * (HIN * HIN);
#pragma unroll 7
        for (int t = 0; t < 49; t++) {
            int py = wy * 7 + jd, px = wx * 7 + jm;
            int sy = (py < HIN) ? py : 158;
            int sx = (px < HIN) ? px : 158;
            As[c * LD1 + j] = __float2half(xb[(c * HIN + sy) * HIN + sx]);
            c += 5; j += 11; jd += 1; jm += 4;
            if (jm >= 7) { jm -= 7; jd += 1; }
            if (j >= 49) { j -= 49; jd -= 7; c += 1; }
        }
    }
    for (int i = tid; i < 2401; i += 256) {
        int p = i / 49, q = i - p * 49;
        Bs[p * LD1 + q] = __float2half(g_attn[(size_t)b * 2401 + i]);
    }
    __syncthreads();

    // ---- MMA1: warp w -> m-tiles {2w, 2w+1} x 7 n-tiles x 4 k-steps ----
    float d[2][7][4];
#pragma unroll
    for (int mt = 0; mt < 2; mt++)
#pragma unroll
        for (int nt = 0; nt < 7; nt++)
#pragma unroll
            for (int r = 0; r < 4; r++) d[mt][nt][r] = 0.f;

#pragma unroll
    for (int ks = 0; ks < 4; ks++) {
        const int kb = ks * 16;
        uint32_t a[2][4];
#pragma unroll
        for (int mt = 0; mt < 2; mt++) {
            const __half* ar = As + (w * 32 + mt * 16 + gid) * LD1 + kb;
            a[mt][0] = *(const uint32_t*)(ar + 2 * t4);
            a[mt][1] = *(const uint32_t*)(ar + 8 * LD1 + 2 * t4);
            a[mt][2] = *(const uint32_t*)(ar + 2 * t4 + 8);
            a[mt][3] = *(const uint32_t*)(ar + 8 * LD1 + 2 * t4 + 8);
        }
#pragma unroll
        for (int nt = 0; nt < 7; nt++) {
            const __half* br = Bs + (nt * 8 + gid) * LD1 + kb;
            uint32_t b0 = *(const uint32_t*)(br + 2 * t4);
            uint32_t b1 = *(const uint32_t*)(br + 2 * t4 + 8);
#pragma unroll
            for (int mt = 0; mt < 2; mt++)
                mma_f16(d[mt][nt][0], d[mt][nt][1], d[mt][nt][2], d[mt][nt][3],
                        a[mt][0], a[mt][1], a[mt][2], a[mt][3], b0, b1);
        }
    }

    // write Y (fp16) into padded Ys[i][c]
#pragma unroll
    for (int mt = 0; mt < 2; mt++) {
        const int ch = w * 32 + mt * 16 + gid;
#pragma unroll
        for (int nt = 0; nt < 7; nt++) {
            const int n0c = nt * 8 + t4 * 2;
            if (n0c < 49) {
                Ys[n0c * LDY + ch]     = __float2half(d[mt][nt][0]);
                Ys[n0c * LDY + ch + 8] = __float2half(d[mt][nt][2]);
            }
            if (n0c + 1 < 49) {
                Ys[(n0c + 1) * LDY + ch]     = __float2half(d[mt][nt][1]);
                Ys[(n0c + 1) * LDY + ch + 8] = __float2half(d[mt][nt][3]);
            }
        }
    }
    __syncthreads();   // Ys complete; As/Bs region now dead -> reuse for Wv chunks

    // ---- MMA2: out = Wv @ Y.  A = Wv chunks (cp.async from g_Wvh), B = Ys. ----
#pragma unroll
    for (int mt = 0; mt < 2; mt++)
#pragma unroll
        for (int nt = 0; nt < 7; nt++)
#pragma unroll
            for (int r = 0; r < 4; r++) d[mt][nt][r] = 0.f;

    auto loadWv = [&](int kc, int buf) {
        const int k0 = kc * 32;
        const uint32_t dst = smb + (buf ? OFF_WV1 : 0) * 2;
#pragma unroll
        for (int t = 0; t < 4; t++) {
            int f = tid + 256 * t;          // 0..1023
            int row = f >> 2, q = f & 3;
            cp_async16(dst + (uint32_t)(row * LDA2 + q * 8) * 2,
                       g_Wvh + row * 256 + k0 + q * 8, 16);
        }
        CP_COMMIT();
    };

    loadWv(0, 0);
    for (int kc = 0; kc < 8; kc++) {
        const int buf = kc & 1;
        if (kc < 7) loadWv(kc + 1, buf ^ 1);
        if (kc < 7) { CP_WAIT(1); } else { CP_WAIT(0); }
        __syncthreads();
        const __half* A = hs + (buf ? OFF_WV1 : 0);
#pragma unroll
        for (int ks = 0; ks < 2; ks++) {
            const int kb = ks * 16;
            uint32_t a[2][4];
#pragma unroll
            for (int mt = 0; mt < 2; mt++) {
                const __half* ar = A + (w * 32 + mt * 16 + gid) * LDA2 + kb;
                a[mt][0] = *(const uint32_t*)(ar + 2 * t4);
                a[mt][1] = *(const uint32_t*)(ar + 8 * LDA2 + 2 * t4);
                a[mt][2] = *(const uint32_t*)(ar + 2 * t4 + 8);
                a[mt][3] = *(const uint32_t*)(ar + 8 * LDA2 + 2 * t4 + 8);
            }
#pragma unroll
            for (int nt = 0; nt < 7; nt++) {
                const __half* br = Ys + (nt * 8 + gid) * LDY + kc * 32 + kb;
                uint32_t b0 = *(const uint32_t*)(br + 2 * t4);
                uint32_t b1 = *(const uint32_t*)(br + 2 * t4 + 8);
#pragma unroll
                for (int mt = 0; mt < 2; mt++)
                    mma_f16(d[mt][nt][0], d[mt][nt][1], d[mt][nt][2], d[mt][nt][3],
                            a[mt][0], a[mt][1], a[mt][2], a[mt][3], b0, b1);
            }
        }
        __syncthreads();
    }

    // epilogue: cropped scatter + bias
#pragma unroll
    for (int mt = 0; mt < 2; mt++) {
#pragma unroll
        for (int hf = 0; hf < 2; hf++) {
            const int ch = w * 32 + mt * 16 + gid + hf * 8;
            const float bias = bv[ch];
            float* obase = out + (size_t)(b * C_ + ch) * (HIN * HIN);
#pragma unroll
            for (int nt = 0; nt < 7; nt++) {
                const int i0 = nt * 8 + t4 * 2;
                if (i0 < 49) {
                    int o = ntab[i0];
                    if (o >= 0) obase[o] = d[mt][nt][hf * 2 + 0] + bias;
                }
                if (i0 + 1 < 49) {
                    int o = ntab[i0 + 1];
                    if (o >= 0) obase[o] = d[mt][nt][hf * 2 + 1] + bias;
                }
            }
        }
    }
}

extern "C" void kernel_launch(void* const* d_in, const int* in_sizes, int n_in,
                              void* d_out, int out_size)
{
    const float* x  = (const float*)d_in[0];
    const float* Wq = (const float*)d_in[1];
    const float* bq = (const float*)d_in[2];
    const float* Wk = (const float*)d_in[3];
    const float* bk = (const float*)d_in[4];
    const float* Wv = (const float*)d_in[5];
    const float* bv = (const float*)d_in[6];
    float* out = (float*)d_out;

    cudaFuncSetAttribute(kA,   cudaFuncAttributeMaxDynamicSharedMemorySize, KA_SMEM);
    cudaFuncSetAttribute(kB,   cudaFuncAttributeMaxDynamicSharedMemorySize, KB_SMEM);
    cudaFuncSetAttribute(kD12, cudaFuncAttributeMaxDynamicSharedMemorySize, KD12_SMEM);

    // kD12 is launch #3 (0-indexed) -> lands in the profiler's capture slot
    kA<<<dim3((NPIX + 127) / 128, B_), 256, KA_SMEM>>>(x, Wq, bq, Wk, bk);
    kB<<<dim3(NH, B_), 256, KB_SMEM>>>();
    kC<<<264, 256>>>(Wv);
    kD12<<<dim3(NH * NH, B_), 256, KD12_SMEM>>>(x, bv, out);
}

// round 13
// speedup vs baseline: 1.0201x; 1.0201x over previous
#include <cuda_runtime.h>
#include <cuda_fp16.h>
#include <cstdint>

// Problem constants
#define B_    8
#define C_    256
#define HIN   160
#define HP    161
#define NH    23          // windows per side
#define WSS   49
#define NPIX  (HP*HP)     // 25921 == 529*49 (window-linear == row-major linear)

typedef unsigned long long ull;

// Scratch (static device arrays — no runtime allocation)
__device__ float  g_qkf[(size_t)B_ * 64 * NPIX];        // q (ch 0..31) + k (ch 32..63)
__device__ float  g_Spart[(size_t)B_ * NH * WSS * WSS]; // per-window-row logit partials
__device__ float  g_attn[(size_t)B_ * WSS * WSS];       // softmax result
__device__ __half g_Yh[(size_t)B_ * NPIX * C_];         // Y[b][n][c], c contiguous, fp16
__device__ __half g_Wvh[C_ * C_];                       // Wv in fp16 (row-major, K contiguous)

// ---- packed f32x2 helpers ----
__device__ __forceinline__ ull pack2(float x, float y) {
    ull r; asm("mov.b64 %0, {%1, %2};" : "=l"(r) : "f"(x), "f"(y)); return r;
}
__device__ __forceinline__ float2 unpack2(ull v) {
    float2 r; asm("mov.b64 {%0, %1}, %2;" : "=f"(r.x), "=f"(r.y) : "l"(v)); return r;
}
__device__ __forceinline__ void fma2(ull &acc, ull a, ull b) {
    asm("fma.rn.f32x2 %0, %1, %2, %0;" : "+l"(acc) : "l"(a), "l"(b));
}
__device__ __forceinline__ uint32_t smem_u32(const void* p) {
    uint32_t a;
    asm("{ .reg .u64 t; cvta.to.shared.u64 t, %1; cvt.u32.u64 %0, t; }" : "=r"(a) : "l"(p));
    return a;
}
// cp.async (LDGSTS)
__device__ __forceinline__ void cp_async16(uint32_t dst, const void* src, int src_size) {
    asm volatile("cp.async.cg.shared.global [%0], [%1], 16, %2;"
                 :: "r"(dst), "l"(src), "r"(src_size) : "memory");
}
#define CP_COMMIT() asm volatile("cp.async.commit_group;" ::: "memory")
#define CP_WAIT(n)  asm volatile("cp.async.wait_group %0;" :: "n"(n) : "memory")

// warp MMA: D(16x8,f32) += A(16x16,f16 row) * B(16x8,f16 col)
__device__ __forceinline__ void mma_f16(float& d0, float& d1, float& d2, float& d3,
                                        uint32_t a0, uint32_t a1, uint32_t a2, uint32_t a3,
                                        uint32_t b0, uint32_t b1) {
    asm volatile("mma.sync.aligned.m16n8k16.row.col.f32.f16.f16.f32 "
                 "{%0,%1,%2,%3}, {%4,%5,%6,%7}, {%8,%9}, {%0,%1,%2,%3};"
                 : "+f"(d0), "+f"(d1), "+f"(d2), "+f"(d3)
                 : "r"(a0), "r"(a1), "r"(a2), "r"(a3), "r"(b0), "r"(b1));
}
// ldmatrix: x4 -> A-fragment (m16k16), x2 -> B-fragment (n8k16)
__device__ __forceinline__ void ldm_x4(uint32_t& r0, uint32_t& r1, uint32_t& r2, uint32_t& r3,
                                       uint32_t addr) {
    asm volatile("ldmatrix.sync.aligned.m8n8.x4.shared.b16 {%0,%1,%2,%3}, [%4];"
                 : "=r"(r0), "=r"(r1), "=r"(r2), "=r"(r3) : "r"(addr));
}
__device__ __forceinline__ void ldm_x2(uint32_t& r0, uint32_t& r1, uint32_t addr) {
    asm volatile("ldmatrix.sync.aligned.m8n8.x2.shared.b16 {%0,%1}, [%2];"
                 : "=r"(r0), "=r"(r1) : "r"(addr));
}

// ---- Kernel A (R6 version): fused q/k 1x1 conv, fp32 FFMA2 ----
#define KA_SMEM ((64 * 256 + 8 * 128) * 4)
__global__ __launch_bounds__(256, 3) void kA(
    const float* __restrict__ x,
    const float* __restrict__ Wq, const float* __restrict__ bq,
    const float* __restrict__ Wk, const float* __restrict__ bk)
{
    extern __shared__ float sm[];
    float* ws = sm;              // 64*256 weights
    float* xs = sm + 64 * 256;   // 8 c-slices x 128 px
    const int b = blockIdx.y;
    const int pxbase = blockIdx.x * 128;
    const int tid = threadIdx.x;

    for (int i = tid; i < 64 * 256; i += 256) {
        int ch = i >> 8, cc = i & 255;
        ws[i] = (ch < 32) ? Wq[ch * 256 + cc] : Wk[(ch - 32) * 256 + cc];
    }
    const int cg = tid >> 4, pg = tid & 15;

    ull acc[4][4];
#pragma unroll
    for (int k = 0; k < 4; k++) {
        int ch = cg * 4 + k;
        float bias = (ch < 32) ? bq[ch] : bk[ch - 32];
#pragma unroll
        for (int m = 0; m < 4; m++) acc[k][m] = pack2(bias, bias);
    }

    for (int c0 = 0; c0 < 256; c0 += 8) {
        __syncthreads();
#pragma unroll
        for (int t = 0; t < 4; t++) {
            int i = tid + 256 * t;
            int cc = i >> 7, px = i & 127;
            int pp = pxbase + px;
            float v = 0.f;
            if (pp < NPIX) {
                int py = pp / HP, pxx = pp - py * HP;
                int sy = (py < HIN) ? py : 158;
                int sx = (pxx < HIN) ? pxx : 158;
                v = x[(((size_t)b * C_ + (c0 + cc)) * HIN + sy) * HIN + sx];
            }
            xs[cc * 128 + px] = v;
        }
        __syncthreads();
#pragma unroll
        for (int cc = 0; cc < 8; cc++) {
            ull w2[4];
#pragma unroll
            for (int k = 0; k < 4; k++) {
                float w = ws[(cg * 4 + k) * 256 + c0 + cc];
                w2[k] = pack2(w, w);
            }
#pragma unroll
            for (int m = 0; m < 4; m++) {
                ull x2 = *(const ull*)(xs + cc * 128 + pg * 2 + 32 * m);
#pragma unroll
                for (int k = 0; k < 4; k++) fma2(acc[k][m], w2[k], x2);
            }
        }
    }
#pragma unroll
    for (int k = 0; k < 4; k++) {
        int ch = cg * 4 + k;
        size_t base = ((size_t)b * 64 + ch) * NPIX;
#pragma unroll
        for (int m = 0; m < 4; m++) {
            float2 v = unpack2(acc[k][m]);
            int pp0 = pxbase + pg * 2 + 32 * m;
            if (pp0 < NPIX)     g_qkf[base + pp0]     = v.x;
            if (pp0 + 1 < NPIX) g_qkf[base + pp0 + 1] = v.y;
        }
    }
}

// ---- Kernel B: logit partials via 7x7 register-tiled outer products ----
#define KB_QK_PAD 3200
#define KB_SMEM ((KB_QK_PAD + 4 * 3136) * 4)   // 62,976 B
__global__ __launch_bounds__(256) void kB()
{
    extern __shared__ float sb[];
    float* qk  = sb;                 // 64 x 49 staged window (+ padding)
    float* red = sb + KB_QK_PAD;     // 4 slices x 64 tiles x 49
    const int b = blockIdx.y, wy = blockIdx.x, tid = threadIdx.x;
    const int slice = tid >> 6;
    const int tile  = tid & 63;
    const int tp = (tile >> 3) * 7;
    const int tq = (tile & 7) * 7;

    if (tid < KB_QK_PAD - 3136) qk[3136 + tid] = 0.f;

    float acc[7][7];
#pragma unroll
    for (int j = 0; j < 7; j++)
#pragma unroll
        for (int jq = 0; jq < 7; jq++) acc[j][jq] = 0.f;

    const int ch0 = tid / 49;
    const int j0  = tid - ch0 * 49;

    for (int wx = 0; wx < NH; wx++) {
        __syncthreads();
        {
            int ch = ch0, j = j0;
            int jd = j / 7, jm = j - jd * 7;
#pragma unroll
            for (int t = 0; t < 13; t++) {
                int i = tid + 256 * t;
                if (i < 3136) {
                    int py = wy * 7 + jd, px = wx * 7 + jm;
                    qk[i] = g_qkf[((size_t)b * 64 + ch) * NPIX + py * HP + px];
                }
                ch += 5; j += 11; jd += 1; jm += 4;
                if (jm >= 7) { jm -= 7; jd += 1; }
                if (j >= 49) { j -= 49; jd -= 7; ch += 1; }
            }
        }
        __syncthreads();
#pragma unroll
        for (int c = 0; c < 8; c++) {
            const float* qrow = qk + (slice * 8 + c) * 49 + tp;
            const float* krow = qk + (32 + slice * 8 + c) * 49 + tq;
            float qv[7], kv[7];
#pragma unroll
            for (int j = 0; j < 7; j++) qv[j] = qrow[j];
#pragma unroll
            for (int j = 0; j < 7; j++) kv[j] = krow[j];
#pragma unroll
            for (int j = 0; j < 7; j++)
#pragma unroll
                for (int jq = 0; jq < 7; jq++)
                    acc[j][jq] = fmaf(qv[j], kv[jq], acc[j][jq]);
        }
    }

    {
        float* r = red + slice * 3136 + tile * 49;
#pragma unroll
        for (int j = 0; j < 7; j++)
#pragma unroll
            for (int jq = 0; jq < 7; jq++) r[j * 7 + jq] = acc[j][jq];
    }
    __syncthreads();
    for (int i = tid; i < 2401; i += 256) {
        int p = i / 49, q = i - (i / 49) * 49;
        int pr = p / 7, j = p - pr * 7;
        int qr = q / 7, jq = q - qr * 7;
        int idx = (pr * 8 + qr) * 49 + j * 7 + jq;
        float s = red[idx] + red[3136 + idx] + red[2 * 3136 + idx] + red[3 * 3136 + idx];
        g_Spart[((size_t)b * NH + wy) * 2401 + i] = s;
    }
}

// ---- Kernel C: softmax (blocks 0..7) + Wv fp16 convert (blocks 8..263) ----
__global__ __launch_bounds__(256) void kC(const float* __restrict__ Wv)
{
    if (blockIdx.x >= 8) {
        int idx = (blockIdx.x - 8) * 256 + threadIdx.x;
        g_Wvh[idx] = __float2half(Wv[idx]);
        return;
    }
    __shared__ float S[2401];
    const int b = blockIdx.x, tid = threadIdx.x;
    for (int i = tid; i < 2401; i += 256) {
        float s = 0.f;
        for (int wy = 0; wy < NH; wy++) s += g_Spart[((size_t)b * NH + wy) * 2401 + i];
        S[i] = s;
    }
    __syncthreads();
    if (tid < 49) {
        const int i = tid;
        float m = -1e30f;
#pragma unroll
        for (int j = 0; j < 49; j++) m = fmaxf(m, S[i * 49 + j]);
        float sum = 0.f;
#pragma unroll
        for (int j = 0; j < 49; j++) sum += expf(S[i * 49 + j] - m);
        float inv = 1.f / sum;
#pragma unroll
        for (int j = 0; j < 49; j++)
            g_attn[(size_t)b * 2401 + i * 49 + j] = expf(S[i * 49 + j] - m) * inv;
    }
}

// ---- Kernel D1 v6: Y = X_win @ attn^T via fp16 mma + ldmatrix + sp-table gather ----
#define LD1 72                                     // padded row length (halfs)
#define KD1_SMEM ((256 * LD1 + 56 * LD1 + 49 * 256) * 2)   // 70,016 B
__global__ __launch_bounds__(256, 2) void kD1(const float* __restrict__ x)
{
    extern __shared__ __half hsm1[];
    __half* As  = hsm1;                    // [c][j] 256 x LD1
    __half* Bs  = hsm1 + 256 * LD1;        // [i][j] 56 x LD1
    __half* Ysh = hsm1 + (256 + 56) * LD1; // [i][c] 49 x 256
    __shared__ int sp[49];
    const int b = blockIdx.y;
    const int win = blockIdx.x;
    const int wy = win / 23, wx = win - wy * 23;
    const int tid = threadIdx.x;
    const int lane = tid & 31, w = tid >> 5;
    const int gid = lane >> 2, t4 = lane & 3;

    // reflect-pad source offsets for this window
    if (tid < 49) {
        int py = wy * 7 + tid / 7, px = wx * 7 + tid % 7;
        int sy = (py < HIN) ? py : 158;
        int sx = (px < HIN) ? px : 158;
        sp[tid] = sy * HIN + sx;
    }
    // zero pad: As j in [48,64), Bs entirely
    for (int i = tid; i < 256 * 8; i += 256) {
        int r = i >> 3, q = i & 7;
        *(uint32_t*)(As + r * LD1 + 48 + q * 2) = 0;
    }
    for (int i = tid; i < 56 * LD1 / 2; i += 256) ((uint32_t*)Bs)[i] = 0;
    __syncthreads();

    // stage X via sp table (incremental c,j walk: i = tid + 256*t; 256 = 5*49+11)
    {
        int c = tid / 49, j = tid - (tid / 49) * 49;
        const float* xb = x + (size_t)b * C_ * (HIN * HIN);
#pragma unroll 7
        for (int t = 0; t < 49; t++) {
            As[c * LD1 + j] = __float2half(xb[c * (HIN * HIN) + sp[j]]);
            c += 5; j += 11;
            if (j >= 49) { j -= 49; c += 1; }
        }
    }
    for (int i = tid; i < 2401; i += 256) {
        int p = i / 49, q = i - p * 49;
        Bs[p * LD1 + q] = __float2half(g_attn[(size_t)b * 2401 + i]);
    }
    __syncthreads();

    // per-lane ldmatrix base addresses
    const uint32_t smbA = smem_u32(As);
    const uint32_t smbB = smem_u32(Bs);
    uint32_t abase[2], bbase[7];
#pragma unroll
    for (int mt = 0; mt < 2; mt++)
        abase[mt] = smbA + (uint32_t)(((w * 32 + mt * 16 + (lane & 15)) * LD1 + (lane >> 4) * 8) * 2);
#pragma unroll
    for (int nt = 0; nt < 7; nt++)
        bbase[nt] = smbB + (uint32_t)(((nt * 8 + (lane & 7)) * LD1 + ((lane >> 3) & 1) * 8) * 2);

    float d[2][7][4];
#pragma unroll
    for (int mt = 0; mt < 2; mt++)
#pragma unroll
        for (int nt = 0; nt < 7; nt++)
#pragma unroll
            for (int r = 0; r < 4; r++) d[mt][nt][r] = 0.f;

#pragma unroll
    for (int ks = 0; ks < 4; ks++) {
        uint32_t a[2][4];
#pragma unroll
        for (int mt = 0; mt < 2; mt++)
            ldm_x4(a[mt][0], a[mt][1], a[mt][2], a[mt][3], abase[mt] + ks * 32);
#pragma unroll
        for (int nt = 0; nt < 7; nt++) {
            uint32_t b0, b1;
            ldm_x2(b0, b1, bbase[nt] + ks * 32);
#pragma unroll
            for (int mt = 0; mt < 2; mt++)
                mma_f16(d[mt][nt][0], d[mt][nt][1], d[mt][nt][2], d[mt][nt][3],
                        a[mt][0], a[mt][1], a[mt][2], a[mt][3], b0, b1);
        }
    }

    // epilogue: frag rows (ch, ch+8), cols (n0c, n0c+1); store to Ysh[i][c]
#pragma unroll
    for (int mt = 0; mt < 2; mt++) {
        const int ch = w * 32 + mt * 16 + gid;
#pragma unroll
        for (int nt = 0; nt < 7; nt++) {
            const int n0c = nt * 8 + t4 * 2;
            if (n0c < 49) {
                Ysh[n0c * 256 + ch]     = __float2half(d[mt][nt][0]);
                Ysh[n0c * 256 + ch + 8] = __float2half(d[mt][nt][2]);
            }
            if (n0c + 1 < 49) {
                Ysh[(n0c + 1) * 256 + ch]     = __float2half(d[mt][nt][1]);
                Ysh[(n0c + 1) * 256 + ch + 8] = __float2half(d[mt][nt][3]);
            }
        }
    }
    __syncthreads();

    // flat coalesced copy: 49*256 halfs == 3136 ull
    {
        ull* ydst = (ull*)(g_Yh + ((size_t)b * NPIX + (size_t)win * 49) * C_);
        const ull* ysrc = (const ull*)Ysh;
        for (int idx = tid; idx < 3136; idx += 256) ydst[idx] = ysrc[idx];
    }
}

// ---- Kernel D2: fp16 mma.sync GEMM + ldmatrix frags ----
#define NT 203
#define LDPH 72
#define CH_HALFS (128 * LDPH)
#define D2_SMEM (4 * CH_HALFS * 2)

__global__ __launch_bounds__(256, 2) void kD2(
    const float* __restrict__ bv, float* __restrict__ out)
{
    extern __shared__ __half hsm[];
    __shared__ int ntab[128];
    const int tid = threadIdx.x;
    const int lane = tid & 31, wid = tid >> 5;
    const int gid = lane >> 2, t4 = lane & 3;
    const int wm = wid >> 2, wn = wid & 3;
    const int b = blockIdx.y;
    const int n0 = blockIdx.x * 128;
    const int mhalf = blockIdx.z;

    const uint32_t smb = smem_u32(hsm);
    const uint32_t sAs[2] = { smb, smb + 2 * CH_HALFS * 2 };
    const uint32_t sBs[2] = { smb + CH_HALFS * 2, smb + 3 * CH_HALFS * 2 };

    {
        int n = n0 + tid;
        int t = -1;
        if (tid < 128 && n < NPIX) {
            int hh = n / HP, ww = n - hh * HP;
            if (hh < HIN && ww < HIN) t = hh * HIN + ww;
        }
        if (tid < 128) ntab[tid] = t;
    }

    const __half* Ag = g_Wvh + (size_t)(mhalf * 128) * 256;
    const __half* Yb = g_Yh + (size_t)b * NPIX * C_;

    auto load_chunk = [&](int kc, int buf) {
        const int k0 = kc * 64;
#pragma unroll
        for (int t = 0; t < 4; t++) {
            int f = tid + 256 * t;
            int row = f >> 3, q = f & 7;
            cp_async16(sAs[buf] + (uint32_t)(row * LDPH + q * 8) * 2,
                       Ag + row * 256 + k0 + q * 8, 16);
        }
#pragma unroll
        for (int t = 0; t < 4; t++) {
            int f = tid + 256 * t;
            int row = f >> 3, q = f & 7;
            int n = n0 + row;
            const __half* src = Yb + (size_t)(n < NPIX ? n : 0) * C_ + k0 + q * 8;
            cp_async16(sBs[buf] + (uint32_t)(row * LDPH + q * 8) * 2,
                       src, (n < NPIX) ? 16 : 0);
        }
        CP_COMMIT();
    };

    // per-lane ldmatrix offsets (within a buffer)
    uint32_t aoff[4], boff[4];
#pragma unroll
    for (int mt = 0; mt < 4; mt++)
        aoff[mt] = (uint32_t)(((wm * 64 + mt * 16 + (lane & 15)) * LDPH + (lane >> 4) * 8) * 2);
#pragma unroll
    for (int nt = 0; nt < 4; nt++)
        boff[nt] = (uint32_t)(((wn * 32 + nt * 8 + (lane & 7)) * LDPH + ((lane >> 3) & 1) * 8) * 2);

    float d[4][4][4];
#pragma unroll
    for (int mt = 0; mt < 4; mt++)
#pragma unroll
        for (int nt = 0; nt < 4; nt++)
#pragma unroll
            for (int r = 0; r < 4; r++) d[mt][nt][r] = 0.f;

    load_chunk(0, 0);
    for (int kc = 0; kc < 4; kc++) {
        const int buf = kc & 1;
        if (kc < 3) load_chunk(kc + 1, buf ^ 1);
        if (kc < 3) { CP_WAIT(1); } else { CP_WAIT(0); }
        __syncthreads();

        const uint32_t aB = sAs[buf], bB = sBs[buf];
#pragma unroll
        for (int ks = 0; ks < 4; ks++) {
            uint32_t a[4][4];
#pragma unroll
            for (int mt = 0; mt < 4; mt++)
                ldm_x4(a[mt][0], a[mt][1], a[mt][2], a[mt][3], aB + aoff[mt] + ks * 32);
#pragma unroll
            for (int nt = 0; nt < 4; nt++) {
                uint32_t b0, b1;
                ldm_x2(b0, b1, bB + boff[nt] + ks * 32);
#pragma unroll
                for (int mt = 0; mt < 4; mt++)
                    mma_f16(d[mt][nt][0], d[mt][nt][1], d[mt][nt][2], d[mt][nt][3],
                            a[mt][0], a[mt][1], a[mt][2], a[mt][3], b0, b1);
            }
        }
        __syncthreads();
    }

#pragma unroll
    for (int mt = 0; mt < 4; mt++) {
#pragma unroll
        for (int hf = 0; hf < 2; hf++) {
            const int ch = mhalf * 128 + wm * 64 + mt * 16 + gid + hf * 8;
            const float bias = bv[ch];
            float* obase = out + (size_t)(b * C_ + ch) * (HIN * HIN);
#pragma unroll
            for (int nt = 0; nt < 4; nt++) {
                const int col = wn * 32 + nt * 8 + t4 * 2;
                const float v0 = d[mt][nt][hf * 2 + 0];
                const float v1 = d[mt][nt][hf * 2 + 1];
                int o0 = ntab[col], o1 = ntab[col + 1];
                if (o0 >= 0) obase[o0] = v0 + bias;
                if (o1 >= 0) obase[o1] = v1 + bias;
            }
        }
    }
}

extern "C" void kernel_launch(void* const* d_in, const int* in_sizes, int n_in,
                              void* d_out, int out_size)
{
    const float* x  = (const float*)d_in[0];
    const float* Wq = (const float*)d_in[1];
    const float* bq = (const float*)d_in[2];
    const float* Wk = (const float*)d_in[3];
    const float* bk = (const float*)d_in[4];
    const float* Wv = (const float*)d_in[5];
    const float* bv = (const float*)d_in[6];
    float* out = (float*)d_out;

    cudaFuncSetAttribute(kA,  cudaFuncAttributeMaxDynamicSharedMemorySize, KA_SMEM);
    cudaFuncSetAttribute(kB,  cudaFuncAttributeMaxDynamicSharedMemorySize, KB_SMEM);
    cudaFuncSetAttribute(kD1, cudaFuncAttributeMaxDynamicSharedMemorySize, KD1_SMEM);
    cudaFuncSetAttribute(kD2, cudaFuncAttributeMaxDynamicSharedMemorySize, D2_SMEM);

    // kD1 is launch #3 (0-indexed) -> profiler capture slot
    kA<<<dim3((NPIX + 127) / 128, B_), 256, KA_SMEM>>>(x, Wq, bq, Wk, bk);
    kB<<<dim3(NH, B_), 256, KB_SMEM>>>();
    kC<<<264, 256>>>(Wv);
    kD1<<<dim3(NH * NH, B_), 256, KD1_SMEM>>>(x);
    kD2<<<dim3(NT, B_, 2), 256, D2_SMEM>>>(bv, out);
}

// round 14
// speedup vs baseline: 1.3450x; 1.3185x over previous
#include <cuda_runtime.h>
#include <cuda_fp16.h>
#include <cstdint>

// Problem constants
#define B_    8
#define C_    256
#define HIN   160
#define HP    161
#define NH    23          // windows per side
#define WSS   49
#define NPIX  (HP*HP)     // 25921 == 529*49 (window-linear == row-major linear)

typedef unsigned long long ull;

// Scratch (static device arrays — no runtime allocation)
__device__ float  g_qkf[(size_t)B_ * 64 * NPIX];        // q (ch 0..31) + k (ch 32..63)
__device__ float  g_Spart[(size_t)B_ * NH * WSS * WSS]; // per-window-row logit partials
__device__ float  g_attn[(size_t)B_ * WSS * WSS];       // softmax result
__device__ __half g_Yh[(size_t)B_ * NPIX * C_];         // Y[b][n][c], c contiguous, fp16
__device__ __half g_Wvh[C_ * C_];                       // Wv in fp16 (row-major, K contiguous)

// ---- packed f32x2 helpers ----
__device__ __forceinline__ ull pack2(float x, float y) {
    ull r; asm("mov.b64 %0, {%1, %2};" : "=l"(r) : "f"(x), "f"(y)); return r;
}
__device__ __forceinline__ float2 unpack2(ull v) {
    float2 r; asm("mov.b64 {%0, %1}, %2;" : "=f"(r.x), "=f"(r.y) : "l"(v)); return r;
}
__device__ __forceinline__ void fma2(ull &acc, ull a, ull b) {
    asm("fma.rn.f32x2 %0, %1, %2, %0;" : "+l"(acc) : "l"(a), "l"(b));
}
__device__ __forceinline__ uint32_t smem_u32(const void* p) {
    uint32_t a;
    asm("{ .reg .u64 t; cvta.to.shared.u64 t, %1; cvt.u32.u64 %0, t; }" : "=r"(a) : "l"(p));
    return a;
}
// cp.async (LDGSTS)
__device__ __forceinline__ void cp_async16(uint32_t dst, const void* src, int src_size) {
    asm volatile("cp.async.cg.shared.global [%0], [%1], 16, %2;"
                 :: "r"(dst), "l"(src), "r"(src_size) : "memory");
}
#define CP_COMMIT() asm volatile("cp.async.commit_group;" ::: "memory")
#define CP_WAIT(n)  asm volatile("cp.async.wait_group %0;" :: "n"(n) : "memory")

// warp MMA: D(16x8,f32) += A(16x16,f16 row) * B(16x8,f16 col)
__device__ __forceinline__ void mma_f16(float& d0, float& d1, float& d2, float& d3,
                                        uint32_t a0, uint32_t a1, uint32_t a2, uint32_t a3,
                                        uint32_t b0, uint32_t b1) {
    asm volatile("mma.sync.aligned.m16n8k16.row.col.f32.f16.f16.f32 "
                 "{%0,%1,%2,%3}, {%4,%5,%6,%7}, {%8,%9}, {%0,%1,%2,%3};"
                 : "+f"(d0), "+f"(d1), "+f"(d2), "+f"(d3)
                 : "r"(a0), "r"(a1), "r"(a2), "r"(a3), "r"(b0), "r"(b1));
}
// ldmatrix: x4 -> A-fragment (m16k16), x2 -> B-fragment (n8k16)
__device__ __forceinline__ void ldm_x4(uint32_t& r0, uint32_t& r1, uint32_t& r2, uint32_t& r3,
                                       uint32_t addr) {
    asm volatile("ldmatrix.sync.aligned.m8n8.x4.shared.b16 {%0,%1,%2,%3}, [%4];"
                 : "=r"(r0), "=r"(r1), "=r"(r2), "=r"(r3) : "r"(addr));
}
__device__ __forceinline__ void ldm_x2(uint32_t& r0, uint32_t& r1, uint32_t addr) {
    asm volatile("ldmatrix.sync.aligned.m8n8.x2.shared.b16 {%0,%1}, [%2];"
                 : "=r"(r0), "=r"(r1) : "r"(addr));
}

// ---- Kernel A (R6 version): fused q/k 1x1 conv, fp32 FFMA2 ----
#define KA_SMEM ((64 * 256 + 8 * 128) * 4)
__global__ __launch_bounds__(256, 3) void kA(
    const float* __restrict__ x,
    const float* __restrict__ Wq, const float* __restrict__ bq,
    const float* __restrict__ Wk, const float* __restrict__ bk)
{
    extern __shared__ float sm[];
    float* ws = sm;              // 64*256 weights
    float* xs = sm + 64 * 256;   // 8 c-slices x 128 px
    const int b = blockIdx.y;
    const int pxbase = blockIdx.x * 128;
    const int tid = threadIdx.x;

    for (int i = tid; i < 64 * 256; i += 256) {
        int ch = i >> 8, cc = i & 255;
        ws[i] = (ch < 32) ? Wq[ch * 256 + cc] : Wk[(ch - 32) * 256 + cc];
    }
    const int cg = tid >> 4, pg = tid & 15;

    ull acc[4][4];
#pragma unroll
    for (int k = 0; k < 4; k++) {
        int ch = cg * 4 + k;
        float bias = (ch < 32) ? bq[ch] : bk[ch - 32];
#pragma unroll
        for (int m = 0; m < 4; m++) acc[k][m] = pack2(bias, bias);
    }

    for (int c0 = 0; c0 < 256; c0 += 8) {
        __syncthreads();
#pragma unroll
        for (int t = 0; t < 4; t++) {
            int i = tid + 256 * t;
            int cc = i >> 7, px = i & 127;
            int pp = pxbase + px;
            float v = 0.f;
            if (pp < NPIX) {
                int py = pp / HP, pxx = pp - py * HP;
                int sy = (py < HIN) ? py : 158;
                int sx = (pxx < HIN) ? pxx : 158;
                v = x[(((size_t)b * C_ + (c0 + cc)) * HIN + sy) * HIN + sx];
            }
            xs[cc * 128 + px] = v;
        }
        __syncthreads();
#pragma unroll
        for (int cc = 0; cc < 8; cc++) {
            ull w2[4];
#pragma unroll
            for (int k = 0; k < 4; k++) {
                float w = ws[(cg * 4 + k) * 256 + c0 + cc];
                w2[k] = pack2(w, w);
            }
#pragma unroll
            for (int m = 0; m < 4; m++) {
                ull x2 = *(const ull*)(xs + cc * 128 + pg * 2 + 32 * m);
#pragma unroll
                for (int k = 0; k < 4; k++) fma2(acc[k][m], w2[k], x2);
            }
        }
    }
#pragma unroll
    for (int k = 0; k < 4; k++) {
        int ch = cg * 4 + k;
        size_t base = ((size_t)b * 64 + ch) * NPIX;
#pragma unroll
        for (int m = 0; m < 4; m++) {
            float2 v = unpack2(acc[k][m]);
            int pp0 = pxbase + pg * 2 + 32 * m;
            if (pp0 < NPIX)     g_qkf[base + pp0]     = v.x;
            if (pp0 + 1 < NPIX) g_qkf[base + pp0 + 1] = v.y;
        }
    }
}

// ---- Kernel B: logit partials via 7x7 register-tiled outer products ----
#define KB_QK_PAD 3200
#define KB_SMEM ((KB_QK_PAD + 4 * 3136) * 4)   // 62,976 B
__global__ __launch_bounds__(256) void kB()
{
    extern __shared__ float sb[];
    float* qk  = sb;                 // 64 x 49 staged window (+ padding)
    float* red = sb + KB_QK_PAD;     // 4 slices x 64 tiles x 49
    const int b = blockIdx.y, wy = blockIdx.x, tid = threadIdx.x;
    const int slice = tid >> 6;
    const int tile  = tid & 63;
    const int tp = (tile >> 3) * 7;
    const int tq = (tile & 7) * 7;

    if (tid < KB_QK_PAD - 3136) qk[3136 + tid] = 0.f;

    float acc[7][7];
#pragma unroll
    for (int j = 0; j < 7; j++)
#pragma unroll
        for (int jq = 0; jq < 7; jq++) acc[j][jq] = 0.f;

    const int ch0 = tid / 49;
    const int j0  = tid - ch0 * 49;

    for (int wx = 0; wx < NH; wx++) {
        __syncthreads();
        {
            int ch = ch0, j = j0;
            int jd = j / 7, jm = j - jd * 7;
#pragma unroll
            for (int t = 0; t < 13; t++) {
                int i = tid + 256 * t;
                if (i < 3136) {
                    int py = wy * 7 + jd, px = wx * 7 + jm;
                    qk[i] = g_qkf[((size_t)b * 64 + ch) * NPIX + py * HP + px];
                }
                ch += 5; j += 11; jd += 1; jm += 4;
                if (jm >= 7) { jm -= 7; jd += 1; }
                if (j >= 49) { j -= 49; jd -= 7; ch += 1; }
            }
        }
        __syncthreads();
#pragma unroll
        for (int c = 0; c < 8; c++) {
            const float* qrow = qk + (slice * 8 + c) * 49 + tp;
            const float* krow = qk + (32 + slice * 8 + c) * 49 + tq;
            float qv[7], kv[7];
#pragma unroll
            for (int j = 0; j < 7; j++) qv[j] = qrow[j];
#pragma unroll
            for (int j = 0; j < 7; j++) kv[j] = krow[j];
#pragma unroll
            for (int j = 0; j < 7; j++)
#pragma unroll
                for (int jq = 0; jq < 7; jq++)
                    acc[j][jq] = fmaf(qv[j], kv[jq], acc[j][jq]);
        }
    }

    {
        float* r = red + slice * 3136 + tile * 49;
#pragma unroll
        for (int j = 0; j < 7; j++)
#pragma unroll
            for (int jq = 0; jq < 7; jq++) r[j * 7 + jq] = acc[j][jq];
    }
    __syncthreads();
    for (int i = tid; i < 2401; i += 256) {
        int p = i / 49, q = i - (i / 49) * 49;
        int pr = p / 7, j = p - pr * 7;
        int qr = q / 7, jq = q - qr * 7;
        int idx = (pr * 8 + qr) * 49 + j * 7 + jq;
        float s = red[idx] + red[3136 + idx] + red[2 * 3136 + idx] + red[3 * 3136 + idx];
        g_Spart[((size_t)b * NH + wy) * 2401 + i] = s;
    }
}

// ---- Kernel C: softmax (blocks 0..7) + Wv fp16 convert (blocks 8..263) ----
__global__ __launch_bounds__(256) void kC(const float* __restrict__ Wv)
{
    if (blockIdx.x >= 8) {
        int idx = (blockIdx.x - 8) * 256 + threadIdx.x;
        g_Wvh[idx] = __float2half(Wv[idx]);
        return;
    }
    __shared__ float S[2401];
    const int b = blockIdx.x, tid = threadIdx.x;
    for (int i = tid; i < 2401; i += 256) {
        float s = 0.f;
        for (int wy = 0; wy < NH; wy++) s += g_Spart[((size_t)b * NH + wy) * 2401 + i];
        S[i] = s;
    }
    __syncthreads();
    if (tid < 49) {
        const int i = tid;
        float m = -1e30f;
#pragma unroll
        for (int j = 0; j < 49; j++) m = fmaxf(m, S[i * 49 + j]);
        float sum = 0.f;
#pragma unroll
        for (int j = 0; j < 49; j++) sum += expf(S[i * 49 + j] - m);
        float inv = 1.f / sum;
#pragma unroll
        for (int j = 0; j < 49; j++)
            g_attn[(size_t)b * 2401 + i * 49 + j] = expf(S[i * 49 + j] - m) * inv;
    }
}

// ---- Kernel D1 (exact R11 v5): Y = X_win @ attn^T as fp16 mma.sync GEMM ----
#define LD1 72                                     // padded row length (halfs)
#define KD1_SMEM ((256 * LD1 + 56 * LD1 + 49 * 256) * 2)   // 70,016 B
__global__ __launch_bounds__(256, 2) void kD1(const float* __restrict__ x)
{
    extern __shared__ __half hsm1[];
    __half* As  = hsm1;                    // [c][j] 256 x LD1
    __half* Bs  = hsm1 + 256 * LD1;        // [i][j] 56 x LD1
    __half* Ysh = hsm1 + (256 + 56) * LD1; // [i][c] 49 x 256
    const int b = blockIdx.y;
    const int win = blockIdx.x;
    const int wy = win / 23, wx = win - wy * 23;
    const int tid = threadIdx.x;
    const int lane = tid & 31, w = tid >> 5;
    const int gid = lane >> 2, t4 = lane & 3;

    // zero pad: As j in [48,64), Bs entirely
    for (int i = tid; i < 256 * 8; i += 256) {
        int r = i >> 3, q = i & 7;
        *(uint32_t*)(As + r * LD1 + 48 + q * 2) = 0;
    }
    for (int i = tid; i < 56 * LD1 / 2; i += 256) ((uint32_t*)Bs)[i] = 0;
    __syncthreads();

    // stage X (gather + fp16 convert, inline address math) and attn
    for (int i = tid; i < 256 * 49; i += 256) {
        int c = i / 49, j = i - c * 49;
        int py = wy * 7 + j / 7, px = wx * 7 + (j % 7);
        int sy = (py < HIN) ? py : 158;
        int sx = (px < HIN) ? px : 158;
        As[c * LD1 + j] = __float2half(x[(((size_t)b * C_ + c) * HIN + sy) * HIN + sx]);
    }
    for (int i = tid; i < 2401; i += 256) {
        int p = i / 49, q = i - p * 49;
        Bs[p * LD1 + q] = __float2half(g_attn[(size_t)b * 2401 + i]);
    }
    __syncthreads();

    float d[2][7][4];
#pragma unroll
    for (int mt = 0; mt < 2; mt++)
#pragma unroll
        for (int nt = 0; nt < 7; nt++)
#pragma unroll
            for (int r = 0; r < 4; r++) d[mt][nt][r] = 0.f;

#pragma unroll
    for (int ks = 0; ks < 4; ks++) {
        const int kb = ks * 16;
        uint32_t a[2][4];
#pragma unroll
        for (int mt = 0; mt < 2; mt++) {
            const __half* ar = As + (w * 32 + mt * 16 + gid) * LD1 + kb;
            a[mt][0] = *(const uint32_t*)(ar + 2 * t4);
            a[mt][1] = *(const uint32_t*)(ar + 8 * LD1 + 2 * t4);
            a[mt][2] = *(const uint32_t*)(ar + 2 * t4 + 8);
            a[mt][3] = *(const uint32_t*)(ar + 8 * LD1 + 2 * t4 + 8);
        }
#pragma unroll
        for (int nt = 0; nt < 7; nt++) {
            const __half* br = Bs + (nt * 8 + gid) * LD1 + kb;
            uint32_t b0 = *(const uint32_t*)(br + 2 * t4);
            uint32_t b1 = *(const uint32_t*)(br + 2 * t4 + 8);
#pragma unroll
            for (int mt = 0; mt < 2; mt++)
                mma_f16(d[mt][nt][0], d[mt][nt][1], d[mt][nt][2], d[mt][nt][3],
                        a[mt][0], a[mt][1], a[mt][2], a[mt][3], b0, b1);
        }
    }

    // epilogue: frag rows (ch, ch+8), cols (n0c, n0c+1); store to Ysh[i][c]
#pragma unroll
    for (int mt = 0; mt < 2; mt++) {
        const int ch = w * 32 + mt * 16 + gid;
#pragma unroll
        for (int nt = 0; nt < 7; nt++) {
            const int n0c = nt * 8 + t4 * 2;
            if (n0c < 49) {
                Ysh[n0c * 256 + ch]     = __float2half(d[mt][nt][0]);
                Ysh[n0c * 256 + ch + 8] = __float2half(d[mt][nt][2]);
            }
            if (n0c + 1 < 49) {
                Ysh[(n0c + 1) * 256 + ch]     = __float2half(d[mt][nt][1]);
                Ysh[(n0c + 1) * 256 + ch + 8] = __float2half(d[mt][nt][3]);
            }
        }
    }
    __syncthreads();

    // flat coalesced copy: 49*256 halfs == 3136 ull
    {
        ull* ydst = (ull*)(g_Yh + ((size_t)b * NPIX + (size_t)win * 49) * C_);
        const ull* ysrc = (const ull*)Ysh;
        for (int idx = tid; idx < 3136; idx += 256) ydst[idx] = ysrc[idx];
    }
}

// ---- Kernel D2: fp16 mma.sync GEMM + ldmatrix frags ----
#define NT 203
#define LDPH 72
#define CH_HALFS (128 * LDPH)
#define D2_SMEM (4 * CH_HALFS * 2)

__global__ __launch_bounds__(256, 2) void kD2(
    const float* __restrict__ bv, float* __restrict__ out)
{
    extern __shared__ __half hsm[];
    __shared__ int ntab[128];
    const int tid = threadIdx.x;
    const int lane = tid & 31, wid = tid >> 5;
    const int gid = lane >> 2, t4 = lane & 3;
    const int wm = wid >> 2, wn = wid & 3;
    const int b = blockIdx.y;
    const int n0 = blockIdx.x * 128;
    const int mhalf = blockIdx.z;

    const uint32_t smb = smem_u32(hsm);
    const uint32_t sAs[2] = { smb, smb + 2 * CH_HALFS * 2 };
    const uint32_t sBs[2] = { smb + CH_HALFS * 2, smb + 3 * CH_HALFS * 2 };

    {
        int n = n0 + tid;
        int t = -1;
        if (tid < 128 && n < NPIX) {
            int hh = n / HP, ww = n - hh * HP;
            if (hh < HIN && ww < HIN) t = hh * HIN + ww;
        }
        if (tid < 128) ntab[tid] = t;
    }

    const __half* Ag = g_Wvh + (size_t)(mhalf * 128) * 256;
    const __half* Yb = g_Yh + (size_t)b * NPIX * C_;

    auto load_chunk = [&](int kc, int buf) {
        const int k0 = kc * 64;
#pragma unroll
        for (int t = 0; t < 4; t++) {
            int f = tid + 256 * t;
            int row = f >> 3, q = f & 7;
            cp_async16(sAs[buf] + (uint32_t)(row * LDPH + q * 8) * 2,
                       Ag + row * 256 + k0 + q * 8, 16);
        }
#pragma unroll
        for (int t = 0; t < 4; t++) {
            int f = tid + 256 * t;
            int row = f >> 3, q = f & 7;
            int n = n0 + row;
            const __half* src = Yb + (size_t)(n < NPIX ? n : 0) * C_ + k0 + q * 8;
            cp_async16(sBs[buf] + (uint32_t)(row * LDPH + q * 8) * 2,
                       src, (n < NPIX) ? 16 : 0);
        }
        CP_COMMIT();
    };

    // per-lane ldmatrix offsets (within a buffer)
    uint32_t aoff[4], boff[4];
#pragma unroll
    for (int mt = 0; mt < 4; mt++)
        aoff[mt] = (uint32_t)(((wm * 64 + mt * 16 + (lane & 15)) * LDPH + (lane >> 4) * 8) * 2);
#pragma unroll
    for (int nt = 0; nt < 4; nt++)
        boff[nt] = (uint32_t)(((wn * 32 + nt * 8 + (lane & 7)) * LDPH + ((lane >> 3) & 1) * 8) * 2);

    float d[4][4][4];
#pragma unroll
    for (int mt = 0; mt < 4; mt++)
#pragma unroll
        for (int nt = 0; nt < 4; nt++)
#pragma unroll
            for (int r = 0; r < 4; r++) d[mt][nt][r] = 0.f;

    load_chunk(0, 0);
    for (int kc = 0; kc < 4; kc++) {
        const int buf = kc & 1;
        if (kc < 3) load_chunk(kc + 1, buf ^ 1);
        if (kc < 3) { CP_WAIT(1); } else { CP_WAIT(0); }
        __syncthreads();

        const uint32_t aB = sAs[buf], bB = sBs[buf];
#pragma unroll
        for (int ks = 0; ks < 4; ks++) {
            uint32_t a[4][4];
#pragma unroll
            for (int mt = 0; mt < 4; mt++)
                ldm_x4(a[mt][0], a[mt][1], a[mt][2], a[mt][3], aB + aoff[mt] + ks * 32);
#pragma unroll
            for (int nt = 0; nt < 4; nt++) {
                uint32_t b0, b1;
                ldm_x2(b0, b1, bB + boff[nt] + ks * 32);
#pragma unroll
                for (int mt = 0; mt < 4; mt++)
                    mma_f16(d[mt][nt][0], d[mt][nt][1], d[mt][nt][2], d[mt][nt][3],
                            a[mt][0], a[mt][1], a[mt][2], a[mt][3], b0, b1);
            }
        }
        __syncthreads();
    }

#pragma unroll
    for (int mt = 0; mt < 4; mt++) {
#pragma unroll
        for (int hf = 0; hf < 2; hf++) {
            const int ch = mhalf * 128 + wm * 64 + mt * 16 + gid + hf * 8;
            const float bias = bv[ch];
            float* obase = out + (size_t)(b * C_ + ch) * (HIN * HIN);
#pragma unroll
            for (int nt = 0; nt < 4; nt++) {
                const int col = wn * 32 + nt * 8 + t4 * 2;
                const float v0 = d[mt][nt][hf * 2 + 0];
                const float v1 = d[mt][nt][hf * 2 + 1];
                int o0 = ntab[col], o1 = ntab[col + 1];
                if (o0 >= 0) obase[o0] = v0 + bias;
                if (o1 >= 0) obase[o1] = v1 + bias;
            }
        }
    }
}

extern "C" void kernel_launch(void* const* d_in, const int* in_sizes, int n_in,
                              void* d_out, int out_size)
{
    const float* x  = (const float*)d_in[0];
    const float* Wq = (const float*)d_in[1];
    const float* bq = (const float*)d_in[2];
    const float* Wk = (const float*)d_in[3];
    const float* bk = (const float*)d_in[4];
    const float* Wv = (const float*)d_in[5];
    const float* bv = (const float*)d_in[6];
    float* out = (float*)d_out;

    cudaFuncSetAttribute(kA,  cudaFuncAttributeMaxDynamicSharedMemorySize, KA_SMEM);
    cudaFuncSetAttribute(kB,  cudaFuncAttributeMaxDynamicSharedMemorySize, KB_SMEM);
    cudaFuncSetAttribute(kD1, cudaFuncAttributeMaxDynamicSharedMemorySize, KD1_SMEM);
    cudaFuncSetAttribute(kD2, cudaFuncAttributeMaxDynamicSharedMemorySize, D2_SMEM);

    // kD1 is launch #3 (0-indexed) -> profiler capture slot
    kA<<<dim3((NPIX + 127) / 128, B_), 256, KA_SMEM>>>(x, Wq, bq, Wk, bk);
    kB<<<dim3(NH, B_), 256, KB_SMEM>>>();
    kC<<<264, 256>>>(Wv);
    kD1<<<dim3(NH * NH, B_), 256, KD1_SMEM>>>(x);
    kD2<<<dim3(NT, B_, 2), 256, D2_SMEM>>>(bv, out);
}

// round 15
// speedup vs baseline: 1.4928x; 1.1098x over previous
#include <cuda_runtime.h>
#include <cuda_fp16.h>
#include <cstdint>

// Problem constants
#define B_    8
#define C_    256
#define HIN   160
#define HP    161
#define NH    23          // windows per side
#define WSS   49
#define NPIX  (HP*HP)     // 25921 == 529*49 (window-linear count == padded pixel count)

typedef unsigned long long ull;

// Scratch (static device arrays — no runtime allocation)
__device__ float  g_qkf[(size_t)B_ * 64 * NPIX];        // q/k features, WINDOW-LINEAR n
__device__ float  g_Spart[(size_t)B_ * NH * WSS * WSS]; // per-window-row logit partials
__device__ float  g_attn[(size_t)B_ * WSS * WSS];       // softmax result
__device__ __half g_xh[(size_t)B_ * NPIX * C_];         // x fp16, window-linear, c contiguous
__device__ __half g_Yh[(size_t)B_ * NPIX * C_];         // Y[b][n][c], c contiguous, fp16
__device__ __half g_Wvh[C_ * C_];                       // Wv in fp16 (row-major, K contiguous)

// ---- packed f32x2 helpers ----
__device__ __forceinline__ ull pack2(float x, float y) {
    ull r; asm("mov.b64 %0, {%1, %2};" : "=l"(r) : "f"(x), "f"(y)); return r;
}
__device__ __forceinline__ float2 unpack2(ull v) {
    float2 r; asm("mov.b64 {%0, %1}, %2;" : "=f"(r.x), "=f"(r.y) : "l"(v)); return r;
}
__device__ __forceinline__ void fma2(ull &acc, ull a, ull b) {
    asm("fma.rn.f32x2 %0, %1, %2, %0;" : "+l"(acc) : "l"(a), "l"(b));
}
__device__ __forceinline__ ull pack_h2(__half2 a, __half2 b) {
    uint32_t ua = *(uint32_t*)&a, ub = *(uint32_t*)&b;
    ull r; asm("mov.b64 %0, {%1, %2};" : "=l"(r) : "r"(ua), "r"(ub)); return r;
}
__device__ __forceinline__ uint32_t smem_u32(const void* p) {
    uint32_t a;
    asm("{ .reg .u64 t; cvta.to.shared.u64 t, %1; cvt.u32.u64 %0, t; }" : "=r"(a) : "l"(p));
    return a;
}
// cp.async (LDGSTS)
__device__ __forceinline__ void cp_async16(uint32_t dst, const void* src, int src_size) {
    asm volatile("cp.async.cg.shared.global [%0], [%1], 16, %2;"
                 :: "r"(dst), "l"(src), "r"(src_size) : "memory");
}
#define CP_COMMIT() asm volatile("cp.async.commit_group;" ::: "memory")
#define CP_WAIT(n)  asm volatile("cp.async.wait_group %0;" :: "n"(n) : "memory")

// warp MMA + ldmatrix
__device__ __forceinline__ void mma_f16(float& d0, float& d1, float& d2, float& d3,
                                        uint32_t a0, uint32_t a1, uint32_t a2, uint32_t a3,
                                        uint32_t b0, uint32_t b1) {
    asm volatile("mma.sync.aligned.m16n8k16.row.col.f32.f16.f16.f32 "
                 "{%0,%1,%2,%3}, {%4,%5,%6,%7}, {%8,%9}, {%0,%1,%2,%3};"
                 : "+f"(d0), "+f"(d1), "+f"(d2), "+f"(d3)
                 : "r"(a0), "r"(a1), "r"(a2), "r"(a3), "r"(b0), "r"(b1));
}
__device__ __forceinline__ void ldm_x4(uint32_t& r0, uint32_t& r1, uint32_t& r2, uint32_t& r3,
                                       uint32_t addr) {
    asm volatile("ldmatrix.sync.aligned.m8n8.x4.shared.b16 {%0,%1,%2,%3}, [%4];"
                 : "=r"(r0), "=r"(r1), "=r"(r2), "=r"(r3) : "r"(addr));
}
__device__ __forceinline__ void ldm_x4t(uint32_t& r0, uint32_t& r1, uint32_t& r2, uint32_t& r3,
                                        uint32_t addr) {
    asm volatile("ldmatrix.sync.aligned.m8n8.x4.trans.shared.b16 {%0,%1,%2,%3}, [%4];"
                 : "=r"(r0), "=r"(r1), "=r"(r2), "=r"(r3) : "r"(addr));
}
__device__ __forceinline__ void ldm_x2(uint32_t& r0, uint32_t& r1, uint32_t addr) {
    asm volatile("ldmatrix.sync.aligned.m8n8.x2.shared.b16 {%0,%1}, [%2];"
                 : "=r"(r0), "=r"(r1) : "r"(addr));
}

// ---- Kernel A: fused q/k conv, WINDOW-LINEAR tiling, emits g_qkf + g_xh ----
#define XSP 130
#define KA_SMEM ((64 * 256 + 8 * XSP) * 4)   // 69,696 B
__global__ __launch_bounds__(256, 3) void kA(
    const float* __restrict__ x,
    const float* __restrict__ Wq, const float* __restrict__ bq,
    const float* __restrict__ Wk, const float* __restrict__ bk)
{
    extern __shared__ float sm[];
    float* ws = sm;              // 64*256 weights
    float* xs = sm + 64 * 256;   // 8 c-slices x XSP
    __shared__ int sp[128];
    const int b = blockIdx.y;
    const int nbase = blockIdx.x * 128;
    const int tid = threadIdx.x;

    for (int i = tid; i < 64 * 256; i += 256) {
        int ch = i >> 8, cc = i & 255;
        ws[i] = (ch < 32) ? Wq[ch * 256 + cc] : Wk[(ch - 32) * 256 + cc];
    }
    if (tid < 128) {
        int n = nbase + tid; if (n >= NPIX) n = NPIX - 1;
        int win = n / 49, j = n - win * 49;
        int wy = win / 23, wx = win - wy * 23;
        int py = wy * 7 + j / 7, px = wx * 7 + j % 7;
        int sy = (py < HIN) ? py : 158;
        int sx = (px < HIN) ? px : 158;
        sp[tid] = sy * HIN + sx;
    }
    __syncthreads();

    const int pxl = tid & 127;
    const int mysp = sp[pxl];
    const int cg = tid >> 4, pg = tid & 15;
    const float* xb = x + (size_t)b * C_ * (HIN * HIN);

    ull acc[4][4];
#pragma unroll
    for (int k = 0; k < 4; k++) {
        int ch = cg * 4 + k;
        float bias = (ch < 32) ? bq[ch] : bk[ch - 32];
#pragma unroll
        for (int m = 0; m < 4; m++) acc[k][m] = pack2(bias, bias);
    }

    const int px2 = tid >> 1, sel = tid & 1;
    __half* xh_dst = (nbase + px2 < NPIX)
        ? (g_xh + ((size_t)b * NPIX + nbase + px2) * C_ + sel * 4) : nullptr;

    for (int c0 = 0; c0 < 256; c0 += 8) {
        __syncthreads();
#pragma unroll
        for (int t = 0; t < 4; t++) {
            int cc = (tid >> 7) + 2 * t;
            xs[cc * XSP + pxl] = xb[(size_t)(c0 + cc) * (HIN * HIN) + mysp];
        }
        __syncthreads();
        // emit g_xh (fp16, 8B per thread, 16B per pixel-pair)
        if (xh_dst) {
            float v0 = xs[(sel * 4 + 0) * XSP + px2];
            float v1 = xs[(sel * 4 + 1) * XSP + px2];
            float v2 = xs[(sel * 4 + 2) * XSP + px2];
            float v3 = xs[(sel * 4 + 3) * XSP + px2];
            *(ull*)(xh_dst + c0) = pack_h2(__floats2half2_rn(v0, v1),
                                           __floats2half2_rn(v2, v3));
        }
#pragma unroll
        for (int cc = 0; cc < 8; cc++) {
            ull w2[4];
#pragma unroll
            for (int k = 0; k < 4; k++) {
                float w = ws[(cg * 4 + k) * 256 + c0 + cc];
                w2[k] = pack2(w, w);
            }
#pragma unroll
            for (int m = 0; m < 4; m++) {
                ull x2 = *(const ull*)(xs + cc * XSP + pg * 2 + 32 * m);
#pragma unroll
                for (int k = 0; k < 4; k++) fma2(acc[k][m], w2[k], x2);
            }
        }
    }
#pragma unroll
    for (int k = 0; k < 4; k++) {
        int ch = cg * 4 + k;
        size_t base = ((size_t)b * 64 + ch) * NPIX;
#pragma unroll
        for (int m = 0; m < 4; m++) {
            float2 v = unpack2(acc[k][m]);
            int pp0 = nbase + pg * 2 + 32 * m;
            if (pp0 < NPIX)     g_qkf[base + pp0]     = v.x;
            if (pp0 + 1 < NPIX) g_qkf[base + pp0 + 1] = v.y;
        }
    }
}

// ---- Kernel B: logit partials (window-linear g_qkf: contiguous 49-runs) ----
#define KB_QK_PAD 3200
#define KB_SMEM ((KB_QK_PAD + 4 * 3136) * 4)   // 62,976 B
__global__ __launch_bounds__(256) void kB()
{
    extern __shared__ float sb[];
    float* qk  = sb;                 // 64 x 49 staged window (+ padding)
    float* red = sb + KB_QK_PAD;     // 4 slices x 64 tiles x 49
    const int b = blockIdx.y, wy = blockIdx.x, tid = threadIdx.x;
    const int slice = tid >> 6;
    const int tile  = tid & 63;
    const int tp = (tile >> 3) * 7;
    const int tq = (tile & 7) * 7;

    if (tid < KB_QK_PAD - 3136) qk[3136 + tid] = 0.f;

    float acc[7][7];
#pragma unroll
    for (int j = 0; j < 7; j++)
#pragma unroll
        for (int jq = 0; jq < 7; jq++) acc[j][jq] = 0.f;

    const float* qkf_b = g_qkf + (size_t)b * 64 * NPIX;

    for (int wx = 0; wx < NH; wx++) {
        const int nw0 = (wy * NH + wx) * 49;
        __syncthreads();
        for (int i = tid; i < 64 * WSS; i += 256) {
            int ch = i / 49, j = i - ch * 49;
            qk[i] = qkf_b[(size_t)ch * NPIX + nw0 + j];
        }
        __syncthreads();
#pragma unroll
        for (int c = 0; c < 8; c++) {
            const float* qrow = qk + (slice * 8 + c) * 49 + tp;
            const float* krow = qk + (32 + slice * 8 + c) * 49 + tq;
            float qv[7], kv[7];
#pragma unroll
            for (int j = 0; j < 7; j++) qv[j] = qrow[j];
#pragma unroll
            for (int j = 0; j < 7; j++) kv[j] = krow[j];
#pragma unroll
            for (int j = 0; j < 7; j++)
#pragma unroll
                for (int jq = 0; jq < 7; jq++)
                    acc[j][jq] = fmaf(qv[j], kv[jq], acc[j][jq]);
        }
    }

    {
        float* r = red + slice * 3136 + tile * 49;
#pragma unroll
        for (int j = 0; j < 7; j++)
#pragma unroll
            for (int jq = 0; jq < 7; jq++) r[j * 7 + jq] = acc[j][jq];
    }
    __syncthreads();
    for (int i = tid; i < 2401; i += 256) {
        int p = i / 49, q = i - (i / 49) * 49;
        int pr = p / 7, j = p - pr * 7;
        int qr = q / 7, jq = q - qr * 7;
        int idx = (pr * 8 + qr) * 49 + j * 7 + jq;
        float s = red[idx] + red[3136 + idx] + red[2 * 3136 + idx] + red[3 * 3136 + idx];
        g_Spart[((size_t)b * NH + wy) * 2401 + i] = s;
    }
}

// ---- Kernel C: softmax (blocks 0..7) + Wv fp16 convert (blocks 8..263) ----
__global__ __launch_bounds__(256) void kC(const float* __restrict__ Wv)
{
    if (blockIdx.x >= 8) {
        int idx = (blockIdx.x - 8) * 256 + threadIdx.x;
        g_Wvh[idx] = __float2half(Wv[idx]);
        return;
    }
    __shared__ float S[2401];
    const int b = blockIdx.x, tid = threadIdx.x;
    for (int i = tid; i < 2401; i += 256) {
        float s = 0.f;
        for (int wy = 0; wy < NH; wy++) s += g_Spart[((size_t)b * NH + wy) * 2401 + i];
        S[i] = s;
    }
    __syncthreads();
    if (tid < 49) {
        const int i = tid;
        float m = -1e30f;
#pragma unroll
        for (int j = 0; j < 49; j++) m = fmaxf(m, S[i * 49 + j]);
        float sum = 0.f;
#pragma unroll
        for (int j = 0; j < 49; j++) sum += expf(S[i * 49 + j] - m);
        float inv = 1.f / sum;
#pragma unroll
        for (int j = 0; j < 49; j++)
            g_attn[(size_t)b * 2401 + i * 49 + j] = expf(S[i * 49 + j] - m) * inv;
    }
}

// ---- Kernel D1 v7: Y = X_win @ attn^T; A from g_xh via cp.async + ldmatrix.trans ----
#define LDX 264                                    // Xs row length (halfs): [j][c]
#define LDB 72                                     // Bs row length
#define KD1_SMEM ((64 * LDX + 56 * LDB + 49 * 256) * 2)   // 66,944 B
__global__ __launch_bounds__(256, 2) void kD1()
{
    extern __shared__ __half hsm1[];
    __half* Xs  = hsm1;                       // [j][c] 64 x LDX (rows 49..63 zero)
    __half* Bs  = hsm1 + 64 * LDX;            // [i][j] 56 x LDB
    __half* Ysh = hsm1 + 64 * LDX + 56 * LDB; // [i][c] 49 x 256
    const int b = blockIdx.y;
    const int win = blockIdx.x;
    const int tid = threadIdx.x;
    const int lane = tid & 31, w = tid >> 5;
    const int gid = lane >> 2, t4 = lane & 3;
    const uint32_t smbX = smem_u32(Xs);

    // zero: Xs rows 49..63, Bs fully
    for (int i = tid; i < 15 * LDX / 2; i += 256) ((uint32_t*)(Xs + 49 * LDX))[i] = 0;
    for (int i = tid; i < 56 * LDB / 2; i += 256) ((uint32_t*)Bs)[i] = 0;
    __syncthreads();

    // stage X rows (coalesced cp.async from g_xh) and attn
#pragma unroll
    for (int t = 0; t < 7; t++) {
        int f = tid + 256 * t;
        if (f < 1568) {
            int row = f >> 5, q = f & 31;
            cp_async16(smbX + (uint32_t)(row * LDX + q * 8) * 2,
                       g_xh + ((size_t)b * NPIX + (size_t)win * 49 + row) * C_ + q * 8, 16);
        }
    }
    CP_COMMIT();
    for (int i = tid; i < 2401; i += 256) {
        int p = i / 49, q = i - p * 49;
        Bs[p * LDB + q] = __float2half(g_attn[(size_t)b * 2401 + i]);
    }
    CP_WAIT(0);
    __syncthreads();

    // A-frag base addrs (ldmatrix.trans from [k=j][m=c] layout)
    uint32_t abase[2];
#pragma unroll
    for (int mt = 0; mt < 2; mt++) {
        int row0 = (lane & 7) + (lane >> 4) * 8;
        int col0 = w * 32 + mt * 16 + ((lane >> 3) & 1) * 8;
        abase[mt] = smbX + (uint32_t)(row0 * LDX + col0) * 2;
    }

    float d[2][7][4];
#pragma unroll
    for (int mt = 0; mt < 2; mt++)
#pragma unroll
        for (int nt = 0; nt < 7; nt++)
#pragma unroll
            for (int r = 0; r < 4; r++) d[mt][nt][r] = 0.f;

#pragma unroll
    for (int ks = 0; ks < 4; ks++) {
        const int kb = ks * 16;
        uint32_t a[2][4];
#pragma unroll
        for (int mt = 0; mt < 2; mt++)
            ldm_x4t(a[mt][0], a[mt][1], a[mt][2], a[mt][3],
                    abase[mt] + (uint32_t)(kb * LDX) * 2);
#pragma unroll
        for (int nt = 0; nt < 7; nt++) {
            const __half* br = Bs + (nt * 8 + gid) * LDB + kb;
            uint32_t b0 = *(const uint32_t*)(br + 2 * t4);
            uint32_t b1 = *(const uint32_t*)(br + 2 * t4 + 8);
#pragma unroll
            for (int mt = 0; mt < 2; mt++)
                mma_f16(d[mt][nt][0], d[mt][nt][1], d[mt][nt][2], d[mt][nt][3],
                        a[mt][0], a[mt][1], a[mt][2], a[mt][3], b0, b1);
        }
    }

    // epilogue: frag rows (ch, ch+8), cols (n0c, n0c+1); store to Ysh[i][c]
#pragma unroll
    for (int mt = 0; mt < 2; mt++) {
        const int ch = w * 32 + mt * 16 + gid;
#pragma unroll
        for (int nt = 0; nt < 7; nt++) {
            const int n0c = nt * 8 + t4 * 2;
            if (n0c < 49) {
                Ysh[n0c * 256 + ch]     = __float2half(d[mt][nt][0]);
                Ysh[n0c * 256 + ch + 8] = __float2half(d[mt][nt][2]);
            }
            if (n0c + 1 < 49) {
                Ysh[(n0c + 1) * 256 + ch]     = __float2half(d[mt][nt][1]);
                Ysh[(n0c + 1) * 256 + ch + 8] = __float2half(d[mt][nt][3]);
            }
        }
    }
    __syncthreads();

    // flat coalesced copy: 49*256 halfs == 3136 ull
    {
        ull* ydst = (ull*)(g_Yh + ((size_t)b * NPIX + (size_t)win * 49) * C_);
        const ull* ysrc = (const ull*)Ysh;
        for (int idx = tid; idx < 3136; idx += 256) ydst[idx] = ysrc[idx];
    }
}

// ---- Kernel D2: fp16 mma.sync GEMM + ldmatrix frags (R14 version) ----
#define NT 203
#define LDPH 72
#define CH_HALFS (128 * LDPH)
#define D2_SMEM (4 * CH_HALFS * 2)

__global__ __launch_bounds__(256, 2) void kD2(
    const float* __restrict__ bv, float* __restrict__ out)
{
    extern __shared__ __half hsm[];
    __shared__ int ntab[128];
    const int tid = threadIdx.x;
    const int lane = tid & 31, wid = tid >> 5;
    const int gid = lane >> 2, t4 = lane & 3;
    const int wm = wid >> 2, wn = wid & 3;
    const int b = blockIdx.y;
    const int n0 = blockIdx.x * 128;
    const int mhalf = blockIdx.z;

    const uint32_t smb = smem_u32(hsm);
    const uint32_t sAs[2] = { smb, smb + 2 * CH_HALFS * 2 };
    const uint32_t sBs[2] = { smb + CH_HALFS * 2, smb + 3 * CH_HALFS * 2 };

    {
        int n = n0 + tid;
        int t = -1;
        if (tid < 128 && n < NPIX) {
            // window-linear n -> output spatial offset (torch-view scramble + crop)
            int hh = n / HP, ww = n - hh * HP;
            if (hh < HIN && ww < HIN) t = hh * HIN + ww;
        }
        if (tid < 128) ntab[tid] = t;
    }

    const __half* Ag = g_Wvh + (size_t)(mhalf * 128) * 256;
    const __half* Yb = g_Yh + (size_t)b * NPIX * C_;

    auto load_chunk = [&](int kc, int buf) {
        const int k0 = kc * 64;
#pragma unroll
        for (int t = 0; t < 4; t++) {
            int f = tid + 256 * t;
            int row = f >> 3, q = f & 7;
            cp_async16(sAs[buf] + (uint32_t)(row * LDPH + q * 8) * 2,
                       Ag + row * 256 + k0 + q * 8, 16);
        }
#pragma unroll
        for (int t = 0; t < 4; t++) {
            int f = tid + 256 * t;
            int row = f >> 3, q = f & 7;
            int n = n0 + row;
            const __half* src = Yb + (size_t)(n < NPIX ? n : 0) * C_ + k0 + q * 8;
            cp_async16(sBs[buf] + (uint32_t)(row * LDPH + q * 8) * 2,
                       src, (n < NPIX) ? 16 : 0);
        }
        CP_COMMIT();
    };

    uint32_t aoff[4], boff[4];
#pragma unroll
    for (int mt = 0; mt < 4; mt++)
        aoff[mt] = (uint32_t)(((wm * 64 + mt * 16 + (lane & 15)) * LDPH + (lane >> 4) * 8) * 2);
#pragma unroll
    for (int nt = 0; nt < 4; nt++)
        boff[nt] = (uint32_t)(((wn * 32 + nt * 8 + (lane & 7)) * LDPH + ((lane >> 3) & 1) * 8) * 2);

    float d[4][4][4];
#pragma unroll
    for (int mt = 0; mt < 4; mt++)
#pragma unroll
        for (int nt = 0; nt < 4; nt++)
#pragma unroll
            for (int r = 0; r < 4; r++) d[mt][nt][r] = 0.f;

    load_chunk(0, 0);
    for (int kc = 0; kc < 4; kc++) {
        const int buf = kc & 1;
        if (kc < 3) load_chunk(kc + 1, buf ^ 1);
        if (kc < 3) { CP_WAIT(1); } else { CP_WAIT(0); }
        __syncthreads();

        const uint32_t aB = sAs[buf], bB = sBs[buf];
#pragma unroll
        for (int ks = 0; ks < 4; ks++) {
            uint32_t a[4][4];
#pragma unroll
            for (int mt = 0; mt < 4; mt++)
                ldm_x4(a[mt][0], a[mt][1], a[mt][2], a[mt][3], aB + aoff[mt] + ks * 32);
#pragma unroll
            for (int nt = 0; nt < 4; nt++) {
                uint32_t b0, b1;
                ldm_x2(b0, b1, bB + boff[nt] + ks * 32);
#pragma unroll
                for (int mt = 0; mt < 4; mt++)
                    mma_f16(d[mt][nt][0], d[mt][nt][1], d[mt][nt][2], d[mt][nt][3],
                            a[mt][0], a[mt][1], a[mt][2], a[mt][3], b0, b1);
            }
        }
        __syncthreads();
    }

#pragma unroll
    for (int mt = 0; mt < 4; mt++) {
#pragma unroll
        for (int hf = 0; hf < 2; hf++) {
            const int ch = mhalf * 128 + wm * 64 + mt * 16 + gid + hf * 8;
            const float bias = bv[ch];
            float* obase = out + (size_t)(b * C_ + ch) * (HIN * HIN);
#pragma unroll
            for (int nt = 0; nt < 4; nt++) {
                const int col = wn * 32 + nt * 8 + t4 * 2;
                const float v0 = d[mt][nt][hf * 2 + 0];
                const float v1 = d[mt][nt][hf * 2 + 1];
                int o0 = ntab[col], o1 = ntab[col + 1];
                if (o0 >= 0) obase[o0] = v0 + bias;
                if (o1 >= 0) obase[o1] = v1 + bias;
            }
        }
    }
}

extern "C" void kernel_launch(void* const* d_in, const int* in_sizes, int n_in,
                              void* d_out, int out_size)
{
    const float* x  = (const float*)d_in[0];
    const float* Wq = (const float*)d_in[1];
    const float* bq = (const float*)d_in[2];
    const float* Wk = (const float*)d_in[3];
    const float* bk = (const float*)d_in[4];
    const float* Wv = (const float*)d_in[5];
    const float* bv = (const float*)d_in[6];
    float* out = (float*)d_out;

    cudaFuncSetAttribute(kA,  cudaFuncAttributeMaxDynamicSharedMemorySize, KA_SMEM);
    cudaFuncSetAttribute(kB,  cudaFuncAttributeMaxDynamicSharedMemorySize, KB_SMEM);
    cudaFuncSetAttribute(kD1, cudaFuncAttributeMaxDynamicSharedMemorySize, KD1_SMEM);
    cudaFuncSetAttribute(kD2, cudaFuncAttributeMaxDynamicSharedMemorySize, D2_SMEM);

    // kD1 is launch #3 (0-indexed) -> profiler capture slot
    kA<<<dim3((NPIX + 127) / 128, B_), 256, KA_SMEM>>>(x, Wq, bq, Wk, bk);
    kB<<<dim3(NH, B_), 256, KB_SMEM>>>();
    kC<<<264, 256>>>(Wv);
    kD1<<<dim3(NH * NH, B_), 256, KD1_SMEM>>>();
    kD2<<<dim3(NT, B_, 2), 256, D2_SMEM>>>(bv, out);
}